// round 1
// baseline (speedup 1.0000x reference)
#include <cuda_runtime.h>
#include <float.h>

// Scratch: logits / probabilities matrix, 8191 rows, padded row stride 8192.
// 8191*8192*4 B ~= 256 MiB, static device .bss (no runtime allocation).
#define PQ   8191          // number of queries / keys (P-1)
#define NDIM 1024          // feature dim
#define LDS  8192          // padded row stride of scratch
__device__ float g_S[(size_t)PQ * LDS];

// ---------------------------------------------------------------------------
// Kernel 1: S[q][k] = sum_n s[q][n] * X[k][n]   (C = A * B^T, both K-major)
// Tiles: BM=BN=128, BK=16, 256 threads, 8x8 register tile per thread.
// ---------------------------------------------------------------------------
__global__ __launch_bounds__(256) void qk_gemm(const float* __restrict__ s,
                                               const float* __restrict__ X) {
    __shared__ float As[16][128];
    __shared__ float Bs[16][128];

    const int bm = blockIdx.y;          // query tile
    const int bn = blockIdx.x;          // key tile
    const int tid = threadIdx.x;
    const int tr = tid >> 4;            // 0..15
    const int tc = tid & 15;            // 0..15

    const int lr = tid >> 2;            // 0..63 (load row)
    const int lc = (tid & 3) * 4;       // 0,4,8,12 (load col group)

    float acc[8][8];
#pragma unroll
    for (int i = 0; i < 8; i++)
#pragma unroll
        for (int j = 0; j < 8; j++) acc[i][j] = 0.f;

    for (int k0 = 0; k0 < NDIM; k0 += 16) {
        // load A tile (s): 128 rows x 16 cols
#pragma unroll
        for (int rr = 0; rr < 2; rr++) {
            const int m = lr + rr * 64;
            const int q = bm * 128 + m;
            float4 v = make_float4(0.f, 0.f, 0.f, 0.f);
            if (q < PQ) v = *(const float4*)(s + (size_t)q * NDIM + k0 + lc);
            As[lc + 0][m] = v.x; As[lc + 1][m] = v.y;
            As[lc + 2][m] = v.z; As[lc + 3][m] = v.w;
        }
        // load B tile (X rows = keys): 128 rows x 16 cols
#pragma unroll
        for (int rr = 0; rr < 2; rr++) {
            const int m = lr + rr * 64;
            const int kkey = bn * 128 + m;
            float4 v = make_float4(0.f, 0.f, 0.f, 0.f);
            if (kkey < PQ) v = *(const float4*)(X + (size_t)kkey * NDIM + k0 + lc);
            Bs[lc + 0][m] = v.x; Bs[lc + 1][m] = v.y;
            Bs[lc + 2][m] = v.z; Bs[lc + 3][m] = v.w;
        }
        __syncthreads();

#pragma unroll
        for (int kk = 0; kk < 16; kk++) {
            float a[8], b[8];
            *(float4*)&a[0] = *(const float4*)&As[kk][tr * 8];
            *(float4*)&a[4] = *(const float4*)&As[kk][tr * 8 + 4];
            *(float4*)&b[0] = *(const float4*)&Bs[kk][tc * 8];
            *(float4*)&b[4] = *(const float4*)&Bs[kk][tc * 8 + 4];
#pragma unroll
            for (int i = 0; i < 8; i++)
#pragma unroll
                for (int j = 0; j < 8; j++) acc[i][j] += a[i] * b[j];
        }
        __syncthreads();
    }

    // store: column index < 8192 always valid (padded stride); guard rows only.
#pragma unroll
    for (int i = 0; i < 8; i++) {
        const int q = bm * 128 + tr * 8 + i;
        if (q < PQ) {
            float* dst = g_S + (size_t)q * LDS + bn * 128 + tc * 8;
            *(float4*)(dst)     = *(const float4*)&acc[i][0];
            *(float4*)(dst + 4) = *(const float4*)&acc[i][4];
        }
    }
}

// ---------------------------------------------------------------------------
// Kernel 2: row softmax over g_S rows (8191 valid cols); sets col 8191 = 0
// so kernel 3 can treat K = 8192 uniformly. Whole row staged in smem.
// ---------------------------------------------------------------------------
__global__ __launch_bounds__(256) void softmax_rows() {
    __shared__ float row[LDS];
    __shared__ float sred[8];

    const int q = blockIdx.x;
    const int tid = threadIdx.x;
    float* r = g_S + (size_t)q * LDS;

    float4* r4 = (float4*)r;
    float4* row4 = (float4*)row;
    for (int i = tid; i < LDS / 4; i += 256) row4[i] = r4[i];
    __syncthreads();
    if (tid == 0) row[PQ] = -FLT_MAX;   // pad element -> exp() = 0
    __syncthreads();

    // max
    float lmax = -FLT_MAX;
    for (int i = tid; i < LDS; i += 256) lmax = fmaxf(lmax, row[i]);
#pragma unroll
    for (int o = 16; o; o >>= 1) lmax = fmaxf(lmax, __shfl_xor_sync(0xffffffffu, lmax, o));
    if ((tid & 31) == 0) sred[tid >> 5] = lmax;
    __syncthreads();
    float m = sred[0];
#pragma unroll
    for (int w = 1; w < 8; w++) m = fmaxf(m, sred[w]);
    __syncthreads();

    // exp + sum
    float lsum = 0.f;
    for (int i = tid; i < LDS; i += 256) {
        float e = __expf(row[i] - m);
        row[i] = e;
        lsum += e;
    }
#pragma unroll
    for (int o = 16; o; o >>= 1) lsum += __shfl_xor_sync(0xffffffffu, lsum, o);
    if ((tid & 31) == 0) sred[tid >> 5] = lsum;
    __syncthreads();
    float tot = 0.f;
#pragma unroll
    for (int w = 0; w < 8; w++) tot += sred[w];
    const float inv = 1.f / tot;

    // scale + write back (col 8191 becomes exactly 0)
    for (int i = tid; i < LDS / 4; i += 256) {
        float4 v = row4[i];
        v.x *= inv; v.y *= inv; v.z *= inv; v.w *= inv;
        r4[i] = v;
    }
}

// ---------------------------------------------------------------------------
// Kernel 3: O[q][n] = sum_k P[q][k] * V[k][n], V[k] = X[k+1]. K loop = 8192
// (P col 8191 == 0); V row 8191 guarded to zero.
// ---------------------------------------------------------------------------
__global__ __launch_bounds__(256) void pv_gemm(const float* __restrict__ X,
                                               float* __restrict__ out) {
    __shared__ float As[16][128];   // P tile, [k][m]
    __shared__ float Bs[16][128];   // V tile, [k][n]

    const int bm = blockIdx.y;      // query tile (64)
    const int bn = blockIdx.x;      // out-col tile (8)
    const int tid = threadIdx.x;
    const int tr = tid >> 4;
    const int tc = tid & 15;

    const int lr = tid >> 2;        // 0..63
    const int lc = (tid & 3) * 4;   // 0,4,8,12

    const int br = tid >> 5;        // 0..7  (B tile row)
    const int bc = (tid & 31) * 4;  // 0..124 (B tile col)

    float acc[8][8];
#pragma unroll
    for (int i = 0; i < 8; i++)
#pragma unroll
        for (int j = 0; j < 8; j++) acc[i][j] = 0.f;

    const float* V = X + NDIM;      // rows 1..8191 of X

    for (int k0 = 0; k0 < LDS; k0 += 16) {
        // A tile: P rows (queries) x 16 k
#pragma unroll
        for (int rr = 0; rr < 2; rr++) {
            const int m = lr + rr * 64;
            const int q = bm * 128 + m;
            float4 v = make_float4(0.f, 0.f, 0.f, 0.f);
            if (q < PQ) v = *(const float4*)(g_S + (size_t)q * LDS + k0 + lc);
            As[lc + 0][m] = v.x; As[lc + 1][m] = v.y;
            As[lc + 2][m] = v.z; As[lc + 3][m] = v.w;
        }
        // B tile: 16 k rows x 128 n cols (coalesced rows of V)
#pragma unroll
        for (int rr = 0; rr < 2; rr++) {
            const int kr = br + rr * 8;
            const int kg = k0 + kr;
            float4 v = make_float4(0.f, 0.f, 0.f, 0.f);
            if (kg < PQ) v = *(const float4*)(V + (size_t)kg * NDIM + bn * 128 + bc);
            *(float4*)&Bs[kr][bc] = v;
        }
        __syncthreads();

#pragma unroll
        for (int kk = 0; kk < 16; kk++) {
            float a[8], b[8];
            *(float4*)&a[0] = *(const float4*)&As[kk][tr * 8];
            *(float4*)&a[4] = *(const float4*)&As[kk][tr * 8 + 4];
            *(float4*)&b[0] = *(const float4*)&Bs[kk][tc * 8];
            *(float4*)&b[4] = *(const float4*)&Bs[kk][tc * 8 + 4];
#pragma unroll
            for (int i = 0; i < 8; i++)
#pragma unroll
                for (int j = 0; j < 8; j++) acc[i][j] += a[i] * b[j];
        }
        __syncthreads();
    }

#pragma unroll
    for (int i = 0; i < 8; i++) {
        const int q = bm * 128 + tr * 8 + i;
        if (q < PQ) {
            float* dst = out + (size_t)q * NDIM + bn * 128 + tc * 8;
            *(float4*)(dst)     = *(const float4*)&acc[i][0];
            *(float4*)(dst + 4) = *(const float4*)&acc[i][4];
        }
    }
}

// ---------------------------------------------------------------------------
extern "C" void kernel_launch(void* const* d_in, const int* in_sizes, int n_in,
                              void* d_out, int out_size) {
    const float* X = (const float*)d_in[0];   // (8192, 1024)
    const float* s = (const float*)d_in[1];   // (8191, 1024)
    float* out = (float*)d_out;               // (8191, 1024)

    {   // K1: logits
        dim3 grid(64, 64);
        qk_gemm<<<grid, 256>>>(s, X);
    }
    {   // K2: row softmax
        softmax_rows<<<PQ, 256>>>();
    }
    {   // K3: probs @ V
        dim3 grid(8, 64);
        pv_gemm<<<grid, 256>>>(X, out);
    }
}

// round 3
// speedup vs baseline: 2.3774x; 2.3774x over previous
#include <cuda_runtime.h>
#include <cuda_bf16.h>
#include <cstdint>
#include <float.h>

#define PQ   8191
#define NDIM 1024
#define LDS  8192

// ---------------- scratch (static device memory, no allocation) ------------
__device__ float         g_S [(size_t)LDS * LDS];     // 8192x8192 fp32 logits
__device__ __nv_bfloat16 g_sh[(size_t)8192 * 1024];
__device__ __nv_bfloat16 g_sl[(size_t)8192 * 1024];
__device__ __nv_bfloat16 g_xh[(size_t)8192 * 1024];
__device__ __nv_bfloat16 g_xl[(size_t)8192 * 1024];
__device__ __nv_bfloat16 g_vth[(size_t)1024 * 8192];  // V^T hi : [n][k]
__device__ __nv_bfloat16 g_vtl[(size_t)1024 * 8192];  // V^T lo
__device__ __nv_bfloat16 g_Ph[(size_t)8192 * 8192];   // probs hi
__device__ __nv_bfloat16 g_Pl[(size_t)8192 * 8192];   // probs lo

// ---------------- helpers ---------------------------------------------------
__device__ __forceinline__ uint32_t smem_to_u32(const void* p) {
    uint32_t a;
    asm("{ .reg .u64 t; cvta.to.shared.u64 t, %1; cvt.u32.u64 %0, t; }" : "=r"(a) : "l"(p));
    return a;
}
__device__ __forceinline__ void cp16(uint32_t s, const void* g) {
    asm volatile("cp.async.cg.shared.global [%0], [%1], 16;" :: "r"(s), "l"(g));
}
#define CP_COMMIT() asm volatile("cp.async.commit_group;" ::: "memory")
#define CP_WAIT1()  asm volatile("cp.async.wait_group 1;" ::: "memory")

#define LDSM_X4(R, ADDR) \
    asm volatile("ldmatrix.sync.aligned.m8n8.x4.shared.b16 {%0,%1,%2,%3}, [%4];" \
        : "=r"((R)[0]), "=r"((R)[1]), "=r"((R)[2]), "=r"((R)[3]) : "r"(ADDR))
#define LDSM_X2(R, ADDR) \
    asm volatile("ldmatrix.sync.aligned.m8n8.x2.shared.b16 {%0,%1}, [%2];" \
        : "=r"((R)[0]), "=r"((R)[1]) : "r"(ADDR))
#define MMA16816(D, A, B) \
    asm volatile("mma.sync.aligned.m16n8k16.row.col.f32.bf16.bf16.f32 " \
        "{%0,%1,%2,%3}, {%4,%5,%6,%7}, {%8,%9}, {%0,%1,%2,%3};" \
        : "+f"((D)[0]), "+f"((D)[1]), "+f"((D)[2]), "+f"((D)[3]) \
        : "r"((A)[0]), "r"((A)[1]), "r"((A)[2]), "r"((A)[3]), "r"((B)[0]), "r"((B)[1]))

// ---------------- prep kernels ---------------------------------------------
__global__ void cvt_split(const float* __restrict__ src, __nv_bfloat16* __restrict__ hi,
                          __nv_bfloat16* __restrict__ lo, size_t nvalid) {
    size_t i = (size_t)blockIdx.x * blockDim.x + threadIdx.x;
    float v = (i < nvalid) ? src[i] : 0.f;
    __nv_bfloat16 h = __float2bfloat16(v);
    hi[i] = h;
    lo[i] = __float2bfloat16(v - __bfloat162float(h));
}

// Vt[n][k] = X[k+1][n] for k < 8191, else 0; split to bf16 hi/lo.
__global__ void transpose_split(const float* __restrict__ X) {
    __shared__ float t[32][33];
    int k0 = blockIdx.x * 32, n0 = blockIdx.y * 32;
    int tx = threadIdx.x, ty = threadIdx.y;            // 32 x 8
    for (int i = ty; i < 32; i += 8) {
        int k = k0 + i;
        float v = 0.f;
        if (k < PQ) v = X[(size_t)(k + 1) * NDIM + n0 + tx];
        t[i][tx] = v;
    }
    __syncthreads();
    for (int i = ty; i < 32; i += 8) {
        int n = n0 + i;
        float v = t[tx][i];
        __nv_bfloat16 h = __float2bfloat16(v);
        g_vth[(size_t)n * LDS + k0 + tx] = h;
        g_vtl[(size_t)n * LDS + k0 + tx] = __float2bfloat16(v - __bfloat162float(h));
    }
}

// ---------------- softmax: g_S row -> g_Ph/g_Pl ----------------------------
__global__ __launch_bounds__(256) void softmax_rows() {
    __shared__ float row[LDS];
    __shared__ float sred[8];
    const int q = blockIdx.x;
    const int tid = threadIdx.x;
    const float* r = g_S + (size_t)q * LDS;

    const float4* r4 = (const float4*)r;
    float4* row4 = (float4*)row;
    for (int i = tid; i < LDS / 4; i += 256) row4[i] = r4[i];
    __syncthreads();
    if (tid == 0) row[PQ] = -1e30f;   // pad key -> prob 0
    __syncthreads();

    float lmax = -FLT_MAX;
    for (int i = tid; i < LDS; i += 256) lmax = fmaxf(lmax, row[i]);
#pragma unroll
    for (int o = 16; o; o >>= 1) lmax = fmaxf(lmax, __shfl_xor_sync(0xffffffffu, lmax, o));
    if ((tid & 31) == 0) sred[tid >> 5] = lmax;
    __syncthreads();
    float m = sred[0];
#pragma unroll
    for (int w = 1; w < 8; w++) m = fmaxf(m, sred[w]);
    __syncthreads();

    float lsum = 0.f;
    for (int i = tid; i < LDS; i += 256) {
        float e = __expf(row[i] - m);
        row[i] = e;
        lsum += e;
    }
#pragma unroll
    for (int o = 16; o; o >>= 1) lsum += __shfl_xor_sync(0xffffffffu, lsum, o);
    if ((tid & 31) == 0) sred[tid >> 5] = lsum;
    __syncthreads();
    float tot = 0.f;
#pragma unroll
    for (int w = 0; w < 8; w++) tot += sred[w];
    const float inv = 1.f / tot;

    for (int i = tid; i < LDS; i += 256) {
        float p = row[i] * inv;
        __nv_bfloat16 h = __float2bfloat16(p);
        g_Ph[(size_t)q * LDS + i] = h;
        g_Pl[(size_t)q * LDS + i] = __float2bfloat16(p - __bfloat162float(h));
    }
}

// ---------------- split-bf16 HMMA GEMM -------------------------------------
// C[128*by : +128][128*bx : +128] = (Ah+Al) @ (Bh+Bl)^T, both operands K-major.
// BK=32, 3-stage cp.async pipeline, 8 warps (2m x 4n), warp tile 64x32.
#define ROWB   80                       // smem bytes per 32-half row (padded)
#define MATB   (128 * ROWB)             // 10240 B per matrix tile
#define STAGEB (4 * MATB)               // Ah|Al|Bh|Bl
#define NSTAGE 3
#define GSMEM  (NSTAGE * STAGEB)        // 122880 B

__global__ __launch_bounds__(256, 1) void mma_gemm(
        const __nv_bfloat16* __restrict__ Ah, const __nv_bfloat16* __restrict__ Al, size_t lda,
        const __nv_bfloat16* __restrict__ Bh, const __nv_bfloat16* __restrict__ Bl, size_t ldb,
        float* __restrict__ C, size_t ldc, int K, int out_rows) {
    extern __shared__ char sm[];
    const uint32_t smb = smem_to_u32(sm);
    const int tid = threadIdx.x, lane = tid & 31, wid = tid >> 5;
    const int wm = wid & 1, wn = wid >> 1;
    const size_t arow0 = (size_t)blockIdx.y * 128;
    const size_t brow0 = (size_t)blockIdx.x * 128;

    float acc[4][4][4];
#pragma unroll
    for (int a = 0; a < 4; a++)
#pragma unroll
        for (int b = 0; b < 4; b++)
#pragma unroll
            for (int c = 0; c < 4; c++) acc[a][b][c] = 0.f;

    auto load_stage = [&](int stg, int k0) {
        const uint32_t base = smb + stg * STAGEB;
#pragma unroll
        for (int c = tid; c < 512; c += 256) {
            const int row = c >> 2, kc = c & 3;
            const uint32_t so = base + row * ROWB + kc * 16;
            const size_t ga = (arow0 + row) * lda + k0 + kc * 8;
            const size_t gb = (brow0 + row) * ldb + k0 + kc * 8;
            cp16(so,            Ah + ga);
            cp16(so + MATB,     Al + ga);
            cp16(so + 2 * MATB, Bh + gb);
            cp16(so + 3 * MATB, Bl + gb);
        }
    };

    load_stage(0, 0);  CP_COMMIT();
    load_stage(1, 32); CP_COMMIT();

    const int nk = K / 32;
    for (int it = 0; it < nk; ++it) {
        CP_WAIT1();
        __syncthreads();
        if (it + 2 < nk) load_stage((it + 2) % NSTAGE, (it + 2) * 32);
        CP_COMMIT();

        const uint32_t base = smb + (it % NSTAGE) * STAGEB;
#pragma unroll
        for (int ks = 0; ks < 2; ks++) {
            const int k0 = ks * 16;
            const uint32_t a_off = (uint32_t)((wm * 64 + (lane & 15)) * ROWB + (k0 + (lane >> 4) * 8) * 2);
            const uint32_t b_off = (uint32_t)((wn * 32 + (lane & 7)) * ROWB + (k0 + ((lane >> 3) & 1) * 8) * 2);
            uint32_t ah[4][4], al[4][4], bh[4][2], bl[4][2];
#pragma unroll
            for (int mi = 0; mi < 4; mi++) LDSM_X4(ah[mi], base + a_off + mi * 16 * ROWB);
#pragma unroll
            for (int mi = 0; mi < 4; mi++) LDSM_X4(al[mi], base + MATB + a_off + mi * 16 * ROWB);
#pragma unroll
            for (int ni = 0; ni < 4; ni++) LDSM_X2(bh[ni], base + 2 * MATB + b_off + ni * 8 * ROWB);
#pragma unroll
            for (int ni = 0; ni < 4; ni++) LDSM_X2(bl[ni], base + 3 * MATB + b_off + ni * 8 * ROWB);
#pragma unroll
            for (int mi = 0; mi < 4; mi++)
#pragma unroll
                for (int ni = 0; ni < 4; ni++) MMA16816(acc[mi][ni], ah[mi], bh[ni]);
#pragma unroll
            for (int mi = 0; mi < 4; mi++)
#pragma unroll
                for (int ni = 0; ni < 4; ni++) MMA16816(acc[mi][ni], ah[mi], bl[ni]);
#pragma unroll
            for (int mi = 0; mi < 4; mi++)
#pragma unroll
                for (int ni = 0; ni < 4; ni++) MMA16816(acc[mi][ni], al[mi], bh[ni]);
        }
    }

    // epilogue: direct fp32 stores (float2 per fragment half)
#pragma unroll
    for (int mi = 0; mi < 4; mi++) {
        const size_t q0 = arow0 + wm * 64 + mi * 16 + (lane >> 2);
        const size_t q1 = q0 + 8;
#pragma unroll
        for (int ni = 0; ni < 4; ni++) {
            const size_t col = brow0 + wn * 32 + ni * 8 + (lane & 3) * 2;
            if ((int)q0 < out_rows)
                *(float2*)&C[q0 * ldc + col] = make_float2(acc[mi][ni][0], acc[mi][ni][1]);
            if ((int)q1 < out_rows)
                *(float2*)&C[q1 * ldc + col] = make_float2(acc[mi][ni][2], acc[mi][ni][3]);
        }
    }
}

// ---------------- launcher -------------------------------------------------
extern "C" void kernel_launch(void* const* d_in, const int* in_sizes, int n_in,
                              void* d_out, int out_size) {
    const float* X = (const float*)d_in[0];   // (8192, 1024)
    const float* s = (const float*)d_in[1];   // (8191, 1024)
    float* out = (float*)d_out;               // (8191, 1024)

    static bool attr_set = false;
    if (!attr_set) {
        cudaFuncSetAttribute(mma_gemm, cudaFuncAttributeMaxDynamicSharedMemorySize, GSMEM);
        attr_set = true;
    }

    void *p_sh, *p_sl, *p_xh, *p_xl, *p_vth, *p_vtl, *p_S, *p_Ph, *p_Pl;
    cudaGetSymbolAddress(&p_sh, g_sh);   cudaGetSymbolAddress(&p_sl, g_sl);
    cudaGetSymbolAddress(&p_xh, g_xh);   cudaGetSymbolAddress(&p_xl, g_xl);
    cudaGetSymbolAddress(&p_vth, g_vth); cudaGetSymbolAddress(&p_vtl, g_vtl);
    cudaGetSymbolAddress(&p_S, g_S);
    cudaGetSymbolAddress(&p_Ph, g_Ph);   cudaGetSymbolAddress(&p_Pl, g_Pl);

    const size_t NE = (size_t)8192 * 1024;

    cvt_split<<<NE / 256, 256>>>(s, (__nv_bfloat16*)p_sh, (__nv_bfloat16*)p_sl, (size_t)PQ * NDIM);
    cvt_split<<<NE / 256, 256>>>(X, (__nv_bfloat16*)p_xh, (__nv_bfloat16*)p_xl, NE);
    transpose_split<<<dim3(256, 32), dim3(32, 8)>>>(X);

    // K1: S = s @ X^T   (M=8192 pad, N=8192, K=1024)
    mma_gemm<<<dim3(64, 64), 256, GSMEM>>>(
        (const __nv_bfloat16*)p_sh, (const __nv_bfloat16*)p_sl, (size_t)NDIM,
        (const __nv_bfloat16*)p_xh, (const __nv_bfloat16*)p_xl, (size_t)NDIM,
        (float*)p_S, (size_t)LDS, NDIM, 8192);

    // K2: softmax rows -> P (bf16 hi/lo), pad col = 0
    softmax_rows<<<PQ, 256>>>();

    // K3: out = P @ V   (M=8192 pad, N=1024, K=8192)
    mma_gemm<<<dim3(8, 64), 256, GSMEM>>>(
        (const __nv_bfloat16*)p_Ph, (const __nv_bfloat16*)p_Pl, (size_t)LDS,
        (const __nv_bfloat16*)p_vth, (const __nv_bfloat16*)p_vtl, (size_t)LDS,
        out, (size_t)NDIM, LDS, PQ);
}

// round 4
// speedup vs baseline: 3.1387x; 1.3202x over previous
#include <cuda_runtime.h>
#include <cuda_fp16.h>
#include <cstdint>
#include <float.h>

#define PQ   8191
#define NDIM 1024
#define LDS  8192

// ---------------- scratch (static device memory, no allocation) ------------
__device__ float  g_S [(size_t)LDS * LDS];      // 8192x8192 fp32 logits
__device__ __half g_sh[(size_t)8192 * 1024];
__device__ __half g_sl[(size_t)8192 * 1024];
__device__ __half g_xh[(size_t)8192 * 1024];
__device__ __half g_xl[(size_t)8192 * 1024];
__device__ __half g_vth[(size_t)1024 * 8192];   // V^T (fp16, single) : [n][k]
__device__ __half g_Ph[(size_t)8192 * 8192];    // probs hi
__device__ __half g_Pl[(size_t)8192 * 8192];    // probs lo

// ---------------- helpers ---------------------------------------------------
__device__ __forceinline__ uint32_t smem_to_u32(const void* p) {
    uint32_t a;
    asm("{ .reg .u64 t; cvta.to.shared.u64 t, %1; cvt.u32.u64 %0, t; }" : "=r"(a) : "l"(p));
    return a;
}
__device__ __forceinline__ void cp16(uint32_t s, const void* g) {
    asm volatile("cp.async.cg.shared.global [%0], [%1], 16;" :: "r"(s), "l"(g));
}
#define CP_COMMIT() asm volatile("cp.async.commit_group;" ::: "memory")
#define CP_WAIT1()  asm volatile("cp.async.wait_group 1;" ::: "memory")

#define LDSM_X4(R, ADDR) \
    asm volatile("ldmatrix.sync.aligned.m8n8.x4.shared.b16 {%0,%1,%2,%3}, [%4];" \
        : "=r"((R)[0]), "=r"((R)[1]), "=r"((R)[2]), "=r"((R)[3]) : "r"(ADDR))
#define LDSM_X2(R, ADDR) \
    asm volatile("ldmatrix.sync.aligned.m8n8.x2.shared.b16 {%0,%1}, [%2];" \
        : "=r"((R)[0]), "=r"((R)[1]) : "r"(ADDR))
#define MMA16816(D, A, B) \
    asm volatile("mma.sync.aligned.m16n8k16.row.col.f32.f16.f16.f32 " \
        "{%0,%1,%2,%3}, {%4,%5,%6,%7}, {%8,%9}, {%0,%1,%2,%3};" \
        : "+f"((D)[0]), "+f"((D)[1]), "+f"((D)[2]), "+f"((D)[3]) \
        : "r"((A)[0]), "r"((A)[1]), "r"((A)[2]), "r"((A)[3]), "r"((B)[0]), "r"((B)[1]))

// ---------------- prep kernels ---------------------------------------------
__global__ void cvt_split(const float* __restrict__ src, __half* __restrict__ hi,
                          __half* __restrict__ lo, size_t nvalid) {
    size_t i = (size_t)blockIdx.x * blockDim.x + threadIdx.x;
    float v = (i < nvalid) ? src[i] : 0.f;
    __half h = __float2half(v);
    hi[i] = h;
    lo[i] = __float2half(v - __half2float(h));
}

// Vt[n][k] = X[k+1][n] for k < 8191, else 0 (single fp16).
__global__ void transpose_half(const float* __restrict__ X) {
    __shared__ float t[32][33];
    int k0 = blockIdx.x * 32, n0 = blockIdx.y * 32;
    int tx = threadIdx.x, ty = threadIdx.y;            // 32 x 8
    for (int i = ty; i < 32; i += 8) {
        int k = k0 + i;
        float v = 0.f;
        if (k < PQ) v = X[(size_t)(k + 1) * NDIM + n0 + tx];
        t[i][tx] = v;
    }
    __syncthreads();
    for (int i = ty; i < 32; i += 8) {
        int n = n0 + i;
        g_vth[(size_t)n * LDS + k0 + tx] = __float2half(t[tx][i]);
    }
}

// ---------------- softmax: g_S row -> g_Ph/g_Pl (fp16 hi/lo) ---------------
__global__ __launch_bounds__(256) void softmax_rows() {
    __shared__ float row[LDS];
    __shared__ float sred[8];
    const int q = blockIdx.x;
    const int tid = threadIdx.x;
    const float* r = g_S + (size_t)q * LDS;

    const float4* r4 = (const float4*)r;
    float4* row4 = (float4*)row;
    for (int i = tid; i < LDS / 4; i += 256) row4[i] = r4[i];
    __syncthreads();
    if (tid == 0) row[PQ] = -1e30f;   // pad key -> prob 0
    __syncthreads();

    float lmax = -FLT_MAX;
    for (int i = tid; i < LDS; i += 256) lmax = fmaxf(lmax, row[i]);
#pragma unroll
    for (int o = 16; o; o >>= 1) lmax = fmaxf(lmax, __shfl_xor_sync(0xffffffffu, lmax, o));
    if ((tid & 31) == 0) sred[tid >> 5] = lmax;
    __syncthreads();
    float m = sred[0];
#pragma unroll
    for (int w = 1; w < 8; w++) m = fmaxf(m, sred[w]);
    __syncthreads();

    float lsum = 0.f;
    for (int i = tid; i < LDS; i += 256) {
        float e = __expf(row[i] - m);
        row[i] = e;
        lsum += e;
    }
#pragma unroll
    for (int o = 16; o; o >>= 1) lsum += __shfl_xor_sync(0xffffffffu, lsum, o);
    if ((tid & 31) == 0) sred[tid >> 5] = lsum;
    __syncthreads();
    float tot = 0.f;
#pragma unroll
    for (int w = 0; w < 8; w++) tot += sred[w];
    const float inv = 1.f / tot;

    for (int i = tid; i < LDS; i += 256) {
        float p = row[i] * inv;
        __half h = __float2half(p);
        g_Ph[(size_t)q * LDS + i] = h;
        g_Pl[(size_t)q * LDS + i] = __float2half(p - __half2float(h));
    }
}

// ---------------- split-fp16 HMMA GEMM -------------------------------------
// C[128*by][128*bx] = split(A) @ split(B)^T, K-major operands, BK=64,
// 3-stage cp.async pipeline, 8 warps (2m x 4n), warp tile 64x32.
// NPASS=3: Ah.Bh + Ah.Bl + Al.Bh   NPASS=2: Ah.Bh + Al.Bh (B single fp16)
#define ROWB   144                      // 64 halves (128B) + 16B pad
#define MATB   (128 * ROWB)             // 18432 B
#define NSTAGE 3

template <int NPASS>
__global__ __launch_bounds__(256, 1) void mma_gemm(
        const __half* __restrict__ Ah, const __half* __restrict__ Al, size_t lda,
        const __half* __restrict__ Bh, const __half* __restrict__ Bl, size_t ldb,
        float* __restrict__ C, size_t ldc, int K, int out_rows) {
    constexpr int NMAT = (NPASS == 3) ? 4 : 3;   // Ah|Al|Bh|(Bl)
    constexpr int STAGEB = NMAT * MATB;
    extern __shared__ char sm[];
    const uint32_t smb = smem_to_u32(sm);
    const int tid = threadIdx.x, lane = tid & 31, wid = tid >> 5;
    const int wm = wid & 1, wn = wid >> 1;
    const size_t arow0 = (size_t)blockIdx.y * 128;
    const size_t brow0 = (size_t)blockIdx.x * 128;

    float acc[4][4][4];
#pragma unroll
    for (int a = 0; a < 4; a++)
#pragma unroll
        for (int b = 0; b < 4; b++)
#pragma unroll
            for (int c = 0; c < 4; c++) acc[a][b][c] = 0.f;

    auto load_stage = [&](int stg, int k0) {
        const uint32_t base = smb + stg * STAGEB;
#pragma unroll
        for (int c = tid; c < 1024; c += 256) {       // 128 rows x 8 chunks
            const int row = c >> 3, kc = c & 7;
            const uint32_t so = base + row * ROWB + kc * 16;
            const size_t ga = (arow0 + row) * lda + k0 + kc * 8;
            const size_t gb = (brow0 + row) * ldb + k0 + kc * 8;
            cp16(so,            Ah + ga);
            cp16(so + MATB,     Al + ga);
            cp16(so + 2 * MATB, Bh + gb);
            if (NPASS == 3) cp16(so + 3 * MATB, Bl + gb);
        }
    };

    load_stage(0, 0);  CP_COMMIT();
    load_stage(1, 64); CP_COMMIT();

    const int nk = K / 64;
    for (int it = 0; it < nk; ++it) {
        CP_WAIT1();
        __syncthreads();
        if (it + 2 < nk) load_stage((it + 2) % NSTAGE, (it + 2) * 64);
        CP_COMMIT();

        const uint32_t base = smb + (it % NSTAGE) * STAGEB;
#pragma unroll
        for (int ks = 0; ks < 4; ks++) {
            const int k0 = ks * 16;
            const uint32_t a_off = (uint32_t)((wm * 64 + (lane & 15)) * ROWB + (k0 + (lane >> 4) * 8) * 2);
            const uint32_t b_off = (uint32_t)((wn * 32 + (lane & 7)) * ROWB + (k0 + ((lane >> 3) & 1) * 8) * 2);
            uint32_t ah[4][4], al[4][4], bh[4][2], bl[4][2];
#pragma unroll
            for (int mi = 0; mi < 4; mi++) LDSM_X4(ah[mi], base + a_off + mi * 16 * ROWB);
#pragma unroll
            for (int mi = 0; mi < 4; mi++) LDSM_X4(al[mi], base + MATB + a_off + mi * 16 * ROWB);
#pragma unroll
            for (int ni = 0; ni < 4; ni++) LDSM_X2(bh[ni], base + 2 * MATB + b_off + ni * 8 * ROWB);
            if (NPASS == 3) {
#pragma unroll
                for (int ni = 0; ni < 4; ni++) LDSM_X2(bl[ni], base + 3 * MATB + b_off + ni * 8 * ROWB);
            }
#pragma unroll
            for (int mi = 0; mi < 4; mi++)
#pragma unroll
                for (int ni = 0; ni < 4; ni++) MMA16816(acc[mi][ni], ah[mi], bh[ni]);
            if (NPASS == 3) {
#pragma unroll
                for (int mi = 0; mi < 4; mi++)
#pragma unroll
                    for (int ni = 0; ni < 4; ni++) MMA16816(acc[mi][ni], ah[mi], bl[ni]);
            }
#pragma unroll
            for (int mi = 0; mi < 4; mi++)
#pragma unroll
                for (int ni = 0; ni < 4; ni++) MMA16816(acc[mi][ni], al[mi], bh[ni]);
        }
    }

    // epilogue: direct fp32 stores
#pragma unroll
    for (int mi = 0; mi < 4; mi++) {
        const size_t q0 = arow0 + wm * 64 + mi * 16 + (lane >> 2);
        const size_t q1 = q0 + 8;
#pragma unroll
        for (int ni = 0; ni < 4; ni++) {
            const size_t col = brow0 + wn * 32 + ni * 8 + (lane & 3) * 2;
            if ((int)q0 < out_rows)
                *(float2*)&C[q0 * ldc + col] = make_float2(acc[mi][ni][0], acc[mi][ni][1]);
            if ((int)q1 < out_rows)
                *(float2*)&C[q1 * ldc + col] = make_float2(acc[mi][ni][2], acc[mi][ni][3]);
        }
    }
}

// ---------------- launcher -------------------------------------------------
extern "C" void kernel_launch(void* const* d_in, const int* in_sizes, int n_in,
                              void* d_out, int out_size) {
    const float* X = (const float*)d_in[0];   // (8192, 1024)
    const float* s = (const float*)d_in[1];   // (8191, 1024)
    float* out = (float*)d_out;               // (8191, 1024)

    const int GS3 = NSTAGE * 4 * MATB;        // 221184 B
    const int GS2 = NSTAGE * 3 * MATB;        // 165888 B

    static bool attr_set = false;
    if (!attr_set) {
        cudaFuncSetAttribute(mma_gemm<3>, cudaFuncAttributeMaxDynamicSharedMemorySize, GS3);
        cudaFuncSetAttribute(mma_gemm<2>, cudaFuncAttributeMaxDynamicSharedMemorySize, GS2);
        attr_set = true;
    }

    void *p_sh, *p_sl, *p_xh, *p_xl, *p_vth, *p_S, *p_Ph, *p_Pl;
    cudaGetSymbolAddress(&p_sh, g_sh);   cudaGetSymbolAddress(&p_sl, g_sl);
    cudaGetSymbolAddress(&p_xh, g_xh);   cudaGetSymbolAddress(&p_xl, g_xl);
    cudaGetSymbolAddress(&p_vth, g_vth);
    cudaGetSymbolAddress(&p_S, g_S);
    cudaGetSymbolAddress(&p_Ph, g_Ph);   cudaGetSymbolAddress(&p_Pl, g_Pl);

    const size_t NE = (size_t)8192 * 1024;

    cvt_split<<<NE / 256, 256>>>(s, (__half*)p_sh, (__half*)p_sl, (size_t)PQ * NDIM);
    cvt_split<<<NE / 256, 256>>>(X, (__half*)p_xh, (__half*)p_xl, NE);
    transpose_half<<<dim3(256, 32), dim3(32, 8)>>>(X);

    // K1: S = s @ X^T   (M=8192 pad, N=8192, K=1024), 3-pass split
    mma_gemm<3><<<dim3(64, 64), 256, GS3>>>(
        (const __half*)p_sh, (const __half*)p_sl, (size_t)NDIM,
        (const __half*)p_xh, (const __half*)p_xl, (size_t)NDIM,
        (float*)p_S, (size_t)LDS, NDIM, 8192);

    // K2: softmax rows -> P (fp16 hi/lo), pad col = 0
    softmax_rows<<<PQ, 256>>>();

    // K3: out = P @ V   (M=8192 pad, N=1024, K=8192), 2-pass (V single fp16)
    mma_gemm<2><<<dim3(8, 64), 256, GS2>>>(
        (const __half*)p_Ph, (const __half*)p_Pl, (size_t)LDS,
        (const __half*)p_vth, (const __half*)nullptr, (size_t)LDS,
        out, (size_t)NDIM, LDS, PQ);
}

// round 6
// speedup vs baseline: 3.3868x; 1.0791x over previous
#include <cuda_runtime.h>
#include <cuda_fp16.h>
#include <cstdint>
#include <float.h>

#define PQ   8191
#define NDIM 1024
#define LDS  8192

// ---------------- scratch (static device memory, no allocation) ------------
__device__ float  g_S [(size_t)LDS * LDS];      // 8192x8192 fp32 logits
__device__ __half g_sh[(size_t)8192 * 1024];
__device__ __half g_sl[(size_t)8192 * 1024];
__device__ __half g_xh[(size_t)8192 * 1024];
__device__ __half g_xl[(size_t)8192 * 1024];
__device__ __half g_vth[(size_t)1024 * 8192];   // V^T (fp16, single) : [n][k]
__device__ __half g_Ph[(size_t)8192 * 8192];    // probs hi
__device__ __half g_Pl[(size_t)8192 * 8192];    // probs lo

// ---------------- helpers ---------------------------------------------------
__device__ __forceinline__ uint32_t smem_to_u32(const void* p) {
    uint32_t a;
    asm("{ .reg .u64 t; cvta.to.shared.u64 t, %1; cvt.u32.u64 %0, t; }" : "=r"(a) : "l"(p));
    return a;
}
__device__ __forceinline__ void cp16(uint32_t s, const void* g) {
    asm volatile("cp.async.cg.shared.global [%0], [%1], 16;" :: "r"(s), "l"(g));
}
#define CP_COMMIT() asm volatile("cp.async.commit_group;" ::: "memory")
#define CP_WAIT1()  asm volatile("cp.async.wait_group 1;" ::: "memory")

#define LDSM_X4(R, ADDR) \
    asm volatile("ldmatrix.sync.aligned.m8n8.x4.shared.b16 {%0,%1,%2,%3}, [%4];" \
        : "=r"((R)[0]), "=r"((R)[1]), "=r"((R)[2]), "=r"((R)[3]) : "r"(ADDR))
#define LDSM_X2(R, ADDR) \
    asm volatile("ldmatrix.sync.aligned.m8n8.x2.shared.b16 {%0,%1}, [%2];" \
        : "=r"((R)[0]), "=r"((R)[1]) : "r"(ADDR))
#define MMA16816(D, A, B) \
    asm volatile("mma.sync.aligned.m16n8k16.row.col.f32.f16.f16.f32 " \
        "{%0,%1,%2,%3}, {%4,%5,%6,%7}, {%8,%9}, {%0,%1,%2,%3};" \
        : "+f"((D)[0]), "+f"((D)[1]), "+f"((D)[2]), "+f"((D)[3]) \
        : "r"((A)[0]), "r"((A)[1]), "r"((A)[2]), "r"((A)[3]), "r"((B)[0]), "r"((B)[1]))

// ---------------- prep kernels ---------------------------------------------
__global__ void cvt_split(const float* __restrict__ src, __half* __restrict__ hi,
                          __half* __restrict__ lo, size_t nvalid) {
    size_t i = (size_t)blockIdx.x * blockDim.x + threadIdx.x;
    float v = (i < nvalid) ? src[i] : 0.f;
    __half h = __float2half(v);
    hi[i] = h;
    lo[i] = __float2half(v - __half2float(h));
}

// Vt[n][k] = X[k+1][n] for k < 8191, else 0 (single fp16).
__global__ void transpose_half(const float* __restrict__ X) {
    __shared__ float t[32][33];
    int k0 = blockIdx.x * 32, n0 = blockIdx.y * 32;
    int tx = threadIdx.x, ty = threadIdx.y;            // 32 x 8
    for (int i = ty; i < 32; i += 8) {
        int k = k0 + i;
        float v = 0.f;
        if (k < PQ) v = X[(size_t)(k + 1) * NDIM + n0 + tx];
        t[i][tx] = v;
    }
    __syncthreads();
    for (int i = ty; i < 32; i += 8) {
        int n = n0 + i;
        g_vth[(size_t)n * LDS + k0 + tx] = __float2half(t[tx][i]);
    }
}

// ---------------- softmax: g_S row -> g_Ph/g_Pl (fp16 hi/lo) ---------------
__global__ __launch_bounds__(256) void softmax_rows() {
    __shared__ float row[LDS];
    __shared__ float sred[8];
    const int q = blockIdx.x;
    const int tid = threadIdx.x;
    const float* r = g_S + (size_t)q * LDS;

    const float4* r4 = (const float4*)r;
    float4* row4 = (float4*)row;
    for (int i = tid; i < LDS / 4; i += 256) row4[i] = r4[i];
    __syncthreads();
    if (tid == 0) row[PQ] = -1e30f;   // pad key -> prob 0
    __syncthreads();

    float lmax = -FLT_MAX;
    for (int i = tid; i < LDS; i += 256) lmax = fmaxf(lmax, row[i]);
#pragma unroll
    for (int o = 16; o; o >>= 1) lmax = fmaxf(lmax, __shfl_xor_sync(0xffffffffu, lmax, o));
    if ((tid & 31) == 0) sred[tid >> 5] = lmax;
    __syncthreads();
    float m = sred[0];
#pragma unroll
    for (int w = 1; w < 8; w++) m = fmaxf(m, sred[w]);
    __syncthreads();

    float lsum = 0.f;
    for (int i = tid; i < LDS; i += 256) {
        float e = __expf(row[i] - m);
        row[i] = e;
        lsum += e;
    }
#pragma unroll
    for (int o = 16; o; o >>= 1) lsum += __shfl_xor_sync(0xffffffffu, lsum, o);
    if ((tid & 31) == 0) sred[tid >> 5] = lsum;
    __syncthreads();
    float tot = 0.f;
#pragma unroll
    for (int w = 0; w < 8; w++) tot += sred[w];
    const float inv = 1.f / tot;

    __half2* ph2 = (__half2*)(g_Ph + (size_t)q * LDS);
    __half2* pl2 = (__half2*)(g_Pl + (size_t)q * LDS);
    for (int i = tid; i < LDS / 2; i += 256) {
        float p0 = row[2 * i] * inv;
        float p1 = row[2 * i + 1] * inv;
        __half h0 = __float2half(p0), h1 = __float2half(p1);
        ph2[i] = __halves2half2(h0, h1);
        pl2[i] = __halves2half2(__float2half(p0 - __half2float(h0)),
                                __float2half(p1 - __half2float(h1)));
    }
}

// ---------------- split-fp16 HMMA GEMM -------------------------------------
// C[128*by][128*bx] = split(A) @ split(B)^T, K-major operands.
// BM=BN=128, BK=32, 128 threads (4 warps, 2x2), warp tile 64x64,
// 2-stage cp.async pipeline, 2 CTAs/SM.
// NPASS=3: Ah.Bh + Ah.Bl + Al.Bh   NPASS=2: Ah.Bh + Al.Bh (B single fp16)
#define ROWB   80                       // 32 halves (64B) + 16B pad (conflict-free: 5 coprime 8)
#define MATB   (128 * ROWB)             // 10240 B per matrix tile
#define NSTAGE 2

template <int NPASS>
__global__ __launch_bounds__(128, 2) void mma_gemm(
        const __half* __restrict__ Ah, const __half* __restrict__ Al, size_t lda,
        const __half* __restrict__ Bh, const __half* __restrict__ Bl, size_t ldb,
        float* __restrict__ C, size_t ldc, int K, int out_rows) {
    constexpr int NMAT = (NPASS == 3) ? 4 : 3;   // Ah|Al|Bh|(Bl)
    constexpr int STAGEB = NMAT * MATB;
    extern __shared__ char sm[];
    const uint32_t smb = smem_to_u32(sm);
    const int tid = threadIdx.x, lane = tid & 31, wid = tid >> 5;
    const int wm = wid & 1, wn = wid >> 1;       // 2x2 warp grid, warp tile 64x64
    const size_t arow0 = (size_t)blockIdx.y * 128;
    const size_t brow0 = (size_t)blockIdx.x * 128;

    float acc[4][8][4];
#pragma unroll
    for (int a = 0; a < 4; a++)
#pragma unroll
        for (int b = 0; b < 8; b++)
#pragma unroll
            for (int c = 0; c < 4; c++) acc[a][b][c] = 0.f;

    auto load_stage = [&](int stg, int k0) {
        const uint32_t base = smb + stg * STAGEB;
#pragma unroll
        for (int c = tid; c < 512; c += 128) {        // 128 rows x 4 16B-chunks
            const int row = c >> 2, kc = c & 3;
            const uint32_t so = base + row * ROWB + kc * 16;
            const size_t ga = (arow0 + row) * lda + k0 + kc * 8;
            const size_t gb = (brow0 + row) * ldb + k0 + kc * 8;
            cp16(so,            Ah + ga);
            cp16(so + MATB,     Al + ga);
            cp16(so + 2 * MATB, Bh + gb);
            if (NPASS == 3) cp16(so + 3 * MATB, Bl + gb);
        }
    };

    const int nk = K / 32;
    load_stage(0, 0);  CP_COMMIT();
    if (nk > 1) load_stage(1, 32);
    CP_COMMIT();

    for (int it = 0; it < nk; ++it) {
        CP_WAIT1();
        __syncthreads();

        const uint32_t base = smb + (it & 1) * STAGEB;
#pragma unroll
        for (int ks = 0; ks < 2; ks++) {
            const int k0 = ks * 16;
            const uint32_t a_off = (uint32_t)((wm * 64 + (lane & 15)) * ROWB + (k0 + (lane >> 4) * 8) * 2);
            const uint32_t b_off = (uint32_t)((wn * 64 + (lane & 7)) * ROWB + (k0 + ((lane >> 3) & 1) * 8) * 2);
            uint32_t ah[4][4], al[4][4], bh[8][2], bl[8][2];
#pragma unroll
            for (int mi = 0; mi < 4; mi++) LDSM_X4(ah[mi], base + a_off + mi * 16 * ROWB);
#pragma unroll
            for (int mi = 0; mi < 4; mi++) LDSM_X4(al[mi], base + MATB + a_off + mi * 16 * ROWB);
#pragma unroll
            for (int ni = 0; ni < 8; ni++) LDSM_X2(bh[ni], base + 2 * MATB + b_off + ni * 8 * ROWB);
            if (NPASS == 3) {
#pragma unroll
                for (int ni = 0; ni < 8; ni++) LDSM_X2(bl[ni], base + 3 * MATB + b_off + ni * 8 * ROWB);
            }
#pragma unroll
            for (int mi = 0; mi < 4; mi++)
#pragma unroll
                for (int ni = 0; ni < 8; ni++) MMA16816(acc[mi][ni], ah[mi], bh[ni]);
            if (NPASS == 3) {
#pragma unroll
                for (int mi = 0; mi < 4; mi++)
#pragma unroll
                    for (int ni = 0; ni < 8; ni++) MMA16816(acc[mi][ni], ah[mi], bl[ni]);
            }
#pragma unroll
            for (int mi = 0; mi < 4; mi++)
#pragma unroll
                for (int ni = 0; ni < 8; ni++) MMA16816(acc[mi][ni], al[mi], bh[ni]);
        }
        __syncthreads();

        if (it + 2 < nk) load_stage(it & 1, (it + 2) * 32);
        CP_COMMIT();
    }

    // epilogue: direct fp32 stores
#pragma unroll
    for (int mi = 0; mi < 4; mi++) {
        const size_t q0 = arow0 + wm * 64 + mi * 16 + (lane >> 2);
        const size_t q1 = q0 + 8;
#pragma unroll
        for (int ni = 0; ni < 8; ni++) {
            const size_t col = brow0 + wn * 64 + ni * 8 + (lane & 3) * 2;
            if ((int)q0 < out_rows)
                *(float2*)&C[q0 * ldc + col] = make_float2(acc[mi][ni][0], acc[mi][ni][1]);
            if ((int)q1 < out_rows)
                *(float2*)&C[q1 * ldc + col] = make_float2(acc[mi][ni][2], acc[mi][ni][3]);
        }
    }
}

// ---------------- launcher -------------------------------------------------
extern "C" void kernel_launch(void* const* d_in, const int* in_sizes, int n_in,
                              void* d_out, int out_size) {
    const float* X = (const float*)d_in[0];   // (8192, 1024)
    const float* s = (const float*)d_in[1];   // (8191, 1024)
    float* out = (float*)d_out;               // (8191, 1024)

    const int GS3 = NSTAGE * 4 * MATB;        // 81920 B
    const int GS2 = NSTAGE * 3 * MATB;        // 61440 B

    static bool attr_set = false;
    if (!attr_set) {
        cudaFuncSetAttribute(mma_gemm<3>, cudaFuncAttributeMaxDynamicSharedMemorySize, GS3);
        cudaFuncSetAttribute(mma_gemm<2>, cudaFuncAttributeMaxDynamicSharedMemorySize, GS2);
        attr_set = true;
    }

    void *p_sh, *p_sl, *p_xh, *p_xl, *p_vth, *p_S, *p_Ph, *p_Pl;
    cudaGetSymbolAddress(&p_sh, g_sh);   cudaGetSymbolAddress(&p_sl, g_sl);
    cudaGetSymbolAddress(&p_xh, g_xh);   cudaGetSymbolAddress(&p_xl, g_xl);
    cudaGetSymbolAddress(&p_vth, g_vth);
    cudaGetSymbolAddress(&p_S, g_S);
    cudaGetSymbolAddress(&p_Ph, g_Ph);   cudaGetSymbolAddress(&p_Pl, g_Pl);

    const size_t NE = (size_t)8192 * 1024;

    cvt_split<<<NE / 256, 256>>>(s, (__half*)p_sh, (__half*)p_sl, (size_t)PQ * NDIM);
    cvt_split<<<NE / 256, 256>>>(X, (__half*)p_xh, (__half*)p_xl, NE);
    transpose_half<<<dim3(256, 32), dim3(32, 8)>>>(X);

    // K1: S = s @ X^T   (M=8192 pad, N=8192, K=1024), 3-pass split
    mma_gemm<3><<<dim3(64, 64), 128, GS3>>>(
        (const __half*)p_sh, (const __half*)p_sl, (size_t)NDIM,
        (const __half*)p_xh, (const __half*)p_xl, (size_t)NDIM,
        (float*)p_S, (size_t)LDS, NDIM, 8192);

    // K2: softmax rows -> P (fp16 hi/lo), pad col = 0
    softmax_rows<<<PQ, 256>>>();

    // K3: out = P @ V   (M=8192 pad, N=1024, K=8192), 2-pass (V single fp16)
    mma_gemm<2><<<dim3(8, 64), 128, GS2>>>(
        (const __half*)p_Ph, (const __half*)p_Pl, (size_t)LDS,
        (const __half*)p_vth, (const __half*)nullptr, (size_t)LDS,
        out, (size_t)NDIM, LDS, PQ);
}